// round 1
// baseline (speedup 1.0000x reference)
#include <cuda_runtime.h>
#include <math.h>

#define NTOK   2048          // B*S
#define DIM    1024
#define HID    4096
#define NEXP   8
#define KTOP   2
#define NROWS  (NTOK*KTOP)   // 4096 routed token-expert pairs

// ---------------- scratch (device globals: no allocation allowed) ----------
__device__ int   g_idx[NTOK*KTOP];      // top-2 expert ids per token
__device__ float g_wgt[NTOK*KTOP];      // softmax weights per token
__device__ int   g_base[NEXP];          // exclusive scan of counts
__device__ int   g_cnt[NEXP];
__device__ int   g_cur[NEXP];           // running counters for assignment
__device__ int   g_loc[NTOK*KTOP];      // (token,k) -> compacted row
__device__ int   g_rowtok[NROWS];       // compacted row -> token
__device__ float g_h[NROWS*HID];        // 64 MB   silu(xW1)*xW3
__device__ float g_y[NROWS*DIM];        // 16 MB   h @ W2^T

// ---------------- K0: gating scores + top-2 + softmax ----------------------
// one warp per token; gate_w staged in shared.
__global__ void k_gate(const float* __restrict__ x, const float* __restrict__ gw) {
    __shared__ float sg[NEXP*DIM];            // 32 KB
    for (int i = threadIdx.x; i < NEXP*DIM; i += blockDim.x) sg[i] = gw[i];
    __syncthreads();

    int warp = threadIdx.x >> 5;
    int lane = threadIdx.x & 31;
    int t = blockIdx.x * (blockDim.x >> 5) + warp;
    if (t >= NTOK) return;

    float s[NEXP];
    #pragma unroll
    for (int e = 0; e < NEXP; e++) s[e] = 0.f;

    const float* xt = x + (size_t)t * DIM;
    for (int i = lane; i < DIM; i += 32) {
        float xv = xt[i];
        #pragma unroll
        for (int e = 0; e < NEXP; e++) s[e] += xv * sg[e*DIM + i];
    }
    #pragma unroll
    for (int off = 16; off; off >>= 1) {
        #pragma unroll
        for (int e = 0; e < NEXP; e++)
            s[e] += __shfl_xor_sync(0xffffffffu, s[e], off);
    }
    if (lane == 0) {
        int i0 = 0; float v0 = s[0];
        #pragma unroll
        for (int e = 1; e < NEXP; e++) if (s[e] > v0) { v0 = s[e]; i0 = e; }
        int i1 = -1; float v1 = -1e30f;
        #pragma unroll
        for (int e = 0; e < NEXP; e++) if (e != i0 && s[e] > v1) { v1 = s[e]; i1 = e; }
        float w1 = 1.f / (1.f + expf(v0 - v1));   // weight of second (v1 <= v0)
        float w0 = 1.f - w1;
        g_idx[t*2+0] = i0;  g_idx[t*2+1] = i1;
        g_wgt[t*2+0] = w0;  g_wgt[t*2+1] = w1;
    }
}

// ---------------- K1: histogram + exclusive scan (single block) ------------
__global__ void k_hist() {
    __shared__ int c[NEXP];
    if (threadIdx.x < NEXP) c[threadIdx.x] = 0;
    __syncthreads();
    for (int i = threadIdx.x; i < NTOK*KTOP; i += blockDim.x)
        atomicAdd(&c[g_idx[i]], 1);
    __syncthreads();
    if (threadIdx.x == 0) {
        int run = 0;
        #pragma unroll
        for (int e = 0; e < NEXP; e++) {
            g_base[e] = run; g_cnt[e] = c[e]; g_cur[e] = 0; run += c[e];
        }
    }
}

// ---------------- K2: assign compacted rows --------------------------------
__global__ void k_assign() {
    int t = blockIdx.x * blockDim.x + threadIdx.x;
    if (t >= NTOK) return;
    #pragma unroll
    for (int k = 0; k < KTOP; k++) {
        int e = g_idx[t*2+k];
        int p = atomicAdd(&g_cur[e], 1);
        int row = g_base[e] + p;
        g_loc[t*2+k] = row;
        g_rowtok[row] = t;
    }
}

// ---------------- GEMM1: h = silu(x W1^T) * (x W3^T) -----------------------
// 64x64 tile, BK=16, 256 threads, 4x4 microtile, two B operands fused.
__global__ __launch_bounds__(256) void k_ffn1(
    const float* __restrict__ x,
    const float* __restrict__ w1,
    const float* __restrict__ w3)
{
    int e    = blockIdx.z;
    int cnt  = g_cnt[e];
    int base = g_base[e];
    int m0   = blockIdx.y * 64;
    if (m0 >= cnt) return;
    int n0   = blockIdx.x * 64;

    __shared__ float As[16][64];
    __shared__ float B1[16][64];
    __shared__ float B3[16][64];

    int tid = threadIdx.x;
    int lr = tid >> 2;            // 0..63: row within tile (load role)
    int lk = (tid & 3) * 4;       // k offset 0/4/8/12
    int tx = tid & 15;            // n microtile
    int ty = tid >> 4;            // m microtile

    int arow = m0 + lr;
    bool avalid = (arow < cnt);
    int tok = avalid ? g_rowtok[base + arow] : 0;
    const float* aptr = x  + (size_t)tok * DIM + lk;
    const float* bptr1 = w1 + ((size_t)e*HID + n0 + lr) * DIM + lk;
    const float* bptr3 = w3 + ((size_t)e*HID + n0 + lr) * DIM + lk;

    float acc1[4][4], acc3[4][4];
    #pragma unroll
    for (int i = 0; i < 4; i++)
        #pragma unroll
        for (int j = 0; j < 4; j++) { acc1[i][j] = 0.f; acc3[i][j] = 0.f; }

    float4 av  = avalid ? *(const float4*)(aptr)  : make_float4(0,0,0,0);
    float4 b1v = *(const float4*)(bptr1);
    float4 b3v = *(const float4*)(bptr3);

    for (int k0 = 0; k0 < DIM; k0 += 16) {
        __syncthreads();
        As[lk+0][lr] = av.x;  As[lk+1][lr] = av.y;  As[lk+2][lr] = av.z;  As[lk+3][lr] = av.w;
        B1[lk+0][lr] = b1v.x; B1[lk+1][lr] = b1v.y; B1[lk+2][lr] = b1v.z; B1[lk+3][lr] = b1v.w;
        B3[lk+0][lr] = b3v.x; B3[lk+1][lr] = b3v.y; B3[lk+2][lr] = b3v.z; B3[lk+3][lr] = b3v.w;
        if (k0 + 16 < DIM) {
            av  = avalid ? *(const float4*)(aptr  + k0 + 16) : make_float4(0,0,0,0);
            b1v = *(const float4*)(bptr1 + k0 + 16);
            b3v = *(const float4*)(bptr3 + k0 + 16);
        }
        __syncthreads();
        #pragma unroll
        for (int kk = 0; kk < 16; kk++) {
            float4 a  = *(const float4*)&As[kk][ty*4];
            float4 p1 = *(const float4*)&B1[kk][tx*4];
            float4 p3 = *(const float4*)&B3[kk][tx*4];
            float am[4] = {a.x, a.y, a.z, a.w};
            float b1a[4] = {p1.x, p1.y, p1.z, p1.w};
            float b3a[4] = {p3.x, p3.y, p3.z, p3.w};
            #pragma unroll
            for (int i = 0; i < 4; i++)
                #pragma unroll
                for (int j = 0; j < 4; j++) {
                    acc1[i][j] += am[i] * b1a[j];
                    acc3[i][j] += am[i] * b3a[j];
                }
        }
    }

    #pragma unroll
    for (int i = 0; i < 4; i++) {
        int m = m0 + ty*4 + i;
        if (m >= cnt) continue;
        size_t row = base + m;
        float4 out;
        float* o = &out.x;
        #pragma unroll
        for (int j = 0; j < 4; j++) {
            float v = acc1[i][j];
            float sig = 1.f / (1.f + expf(-v));
            o[j] = v * sig * acc3[i][j];
        }
        *(float4*)&g_h[row*HID + n0 + tx*4] = out;
    }
}

// ---------------- GEMM2: y = h W2^T  (N=1024, K=4096) ----------------------
__global__ __launch_bounds__(256) void k_ffn2(const float* __restrict__ w2)
{
    int e    = blockIdx.z;
    int cnt  = g_cnt[e];
    int base = g_base[e];
    int m0   = blockIdx.y * 64;
    if (m0 >= cnt) return;
    int n0   = blockIdx.x * 64;

    __shared__ float As[16][64];
    __shared__ float Bs[16][64];

    int tid = threadIdx.x;
    int lr = tid >> 2;
    int lk = (tid & 3) * 4;
    int tx = tid & 15;
    int ty = tid >> 4;

    int arow = m0 + lr;
    bool avalid = (arow < cnt);
    size_t hrow = (size_t)(base + (avalid ? arow : 0));
    const float* aptr = g_h + hrow * HID + lk;
    const float* bptr = w2 + ((size_t)e*DIM + n0 + lr) * HID + lk;

    float acc[4][4];
    #pragma unroll
    for (int i = 0; i < 4; i++)
        #pragma unroll
        for (int j = 0; j < 4; j++) acc[i][j] = 0.f;

    float4 av = avalid ? *(const float4*)(aptr) : make_float4(0,0,0,0);
    float4 bv = *(const float4*)(bptr);

    for (int k0 = 0; k0 < HID; k0 += 16) {
        __syncthreads();
        As[lk+0][lr] = av.x; As[lk+1][lr] = av.y; As[lk+2][lr] = av.z; As[lk+3][lr] = av.w;
        Bs[lk+0][lr] = bv.x; Bs[lk+1][lr] = bv.y; Bs[lk+2][lr] = bv.z; Bs[lk+3][lr] = bv.w;
        if (k0 + 16 < HID) {
            av = avalid ? *(const float4*)(aptr + k0 + 16) : make_float4(0,0,0,0);
            bv = *(const float4*)(bptr + k0 + 16);
        }
        __syncthreads();
        #pragma unroll
        for (int kk = 0; kk < 16; kk++) {
            float4 a = *(const float4*)&As[kk][ty*4];
            float4 b = *(const float4*)&Bs[kk][tx*4];
            float am[4] = {a.x, a.y, a.z, a.w};
            float bm[4] = {b.x, b.y, b.z, b.w};
            #pragma unroll
            for (int i = 0; i < 4; i++)
                #pragma unroll
                for (int j = 0; j < 4; j++)
                    acc[i][j] += am[i] * bm[j];
        }
    }

    #pragma unroll
    for (int i = 0; i < 4; i++) {
        int m = m0 + ty*4 + i;
        if (m >= cnt) continue;
        size_t row = base + m;
        float4 out = make_float4(acc[i][0], acc[i][1], acc[i][2], acc[i][3]);
        *(float4*)&g_y[row*DIM + n0 + tx*4] = out;
    }
}

// ---------------- K5: weighted combine -------------------------------------
__global__ void k_combine(float* __restrict__ out) {
    int i = blockIdx.x * blockDim.x + threadIdx.x;   // over NTOK*DIM/4
    if (i >= NTOK * (DIM/4)) return;
    int t  = i / (DIM/4);
    int dq = i % (DIM/4);
    float w0 = g_wgt[t*2+0], w1 = g_wgt[t*2+1];
    int r0 = g_loc[t*2+0],  r1 = g_loc[t*2+1];
    float4 y0 = *(const float4*)&g_y[(size_t)r0*DIM + dq*4];
    float4 y1 = *(const float4*)&g_y[(size_t)r1*DIM + dq*4];
    float4 o;
    o.x = w0*y0.x + w1*y1.x;
    o.y = w0*y0.y + w1*y1.y;
    o.z = w0*y0.z + w1*y1.z;
    o.w = w0*y0.w + w1*y1.w;
    *(float4*)(out + (size_t)i*4) = o;
}

// ---------------- launcher -------------------------------------------------
extern "C" void kernel_launch(void* const* d_in, const int* in_sizes, int n_in,
                              void* d_out, int out_size) {
    const float* x  = (const float*)d_in[0];
    const float* gw = (const float*)d_in[1];
    const float* w1 = (const float*)d_in[2];
    const float* w2 = (const float*)d_in[3];
    const float* w3 = (const float*)d_in[4];
    float* out = (float*)d_out;

    k_gate<<<NTOK/8, 256>>>(x, gw);
    k_hist<<<1, 256>>>();
    k_assign<<<NTOK/256, 256>>>();

    dim3 g1(HID/64, NTOK/64, NEXP);    // n-tiles, m-tiles (max), experts
    k_ffn1<<<g1, 256>>>(x, w1, w3);

    dim3 g2(DIM/64, NTOK/64, NEXP);
    k_ffn2<<<g2, 256>>>(w2);

    k_combine<<<(NTOK*(DIM/4) + 255)/256, 256>>>(out);
}

// round 10
// speedup vs baseline: 3.0657x; 3.0657x over previous
#include <cuda_runtime.h>
#include <math.h>
#include <stdint.h>

#define NTOK   2048
#define DIM    1024
#define HID    4096
#define NEXP   8
#define KTOP   2
#define NROWS  (NTOK*KTOP)
#define BK     32

// ---------------- scratch ----------------
__device__ int   g_idx[NTOK*KTOP];
__device__ float g_wgt[NTOK*KTOP];
__device__ int   g_base[NEXP];
__device__ int   g_cnt[NEXP];
__device__ int   g_cur[NEXP];
__device__ int   g_loc[NTOK*KTOP];
__device__ int   g_rowtok[NROWS];
__device__ float g_h[(size_t)NROWS*HID];   // tf32-rounded bits
__device__ float g_y[(size_t)NROWS*DIM];

// ---------------- helpers ----------------
__device__ __forceinline__ uint32_t rna1(float f) {
    uint32_t u; asm("cvt.rna.tf32.f32 %0, %1;" : "=r"(u) : "f"(f)); return u;
}
__device__ __forceinline__ uint4 rna4(float4 v) {
    uint4 u; u.x=rna1(v.x); u.y=rna1(v.y); u.z=rna1(v.z); u.w=rna1(v.w); return u;
}
// m16n8k8 tf32 HMMA (sm_80+, valid on sm_103 base target)
__device__ __forceinline__ void mma8(float* d, const uint32_t* a, const uint32_t* b) {
    asm volatile(
        "mma.sync.aligned.m16n8k8.row.col.f32.tf32.tf32.f32 "
        "{%0,%1,%2,%3}, {%4,%5,%6,%7}, {%8,%9}, {%0,%1,%2,%3};\n"
        : "+f"(d[0]), "+f"(d[1]), "+f"(d[2]), "+f"(d[3])
        : "r"(a[0]), "r"(a[1]), "r"(a[2]), "r"(a[3]), "r"(b[0]), "r"(b[1]));
}

// ---------------- K0: gate ----------------
__global__ void k_gate(const float* __restrict__ x, const float* __restrict__ gw) {
    __shared__ float sg[NEXP*DIM];
    for (int i = threadIdx.x; i < NEXP*DIM; i += blockDim.x) sg[i] = gw[i];
    __syncthreads();
    int warp = threadIdx.x >> 5, lane = threadIdx.x & 31;
    int t = blockIdx.x * (blockDim.x >> 5) + warp;
    if (t >= NTOK) return;
    float s[NEXP];
    #pragma unroll
    for (int e = 0; e < NEXP; e++) s[e] = 0.f;
    const float* xt = x + (size_t)t * DIM;
    for (int i = lane; i < DIM; i += 32) {
        float xv = xt[i];
        #pragma unroll
        for (int e = 0; e < NEXP; e++) s[e] += xv * sg[e*DIM + i];
    }
    #pragma unroll
    for (int off = 16; off; off >>= 1)
        #pragma unroll
        for (int e = 0; e < NEXP; e++) s[e] += __shfl_xor_sync(0xffffffffu, s[e], off);
    if (lane == 0) {
        int i0 = 0; float v0 = s[0];
        #pragma unroll
        for (int e = 1; e < NEXP; e++) if (s[e] > v0) { v0 = s[e]; i0 = e; }
        int i1 = -1; float v1 = -1e30f;
        #pragma unroll
        for (int e = 0; e < NEXP; e++) if (e != i0 && s[e] > v1) { v1 = s[e]; i1 = e; }
        float w1 = 1.f / (1.f + expf(v0 - v1));
        g_idx[t*2+0] = i0;  g_idx[t*2+1] = i1;
        g_wgt[t*2+0] = 1.f - w1;  g_wgt[t*2+1] = w1;
    }
}

// ---------------- K1/K2: histogram + assign ----------------
__global__ void k_hist() {
    __shared__ int c[NEXP];
    if (threadIdx.x < NEXP) c[threadIdx.x] = 0;
    __syncthreads();
    for (int i = threadIdx.x; i < NTOK*KTOP; i += blockDim.x) atomicAdd(&c[g_idx[i]], 1);
    __syncthreads();
    if (threadIdx.x == 0) {
        int run = 0;
        #pragma unroll
        for (int e = 0; e < NEXP; e++) { g_base[e] = run; g_cnt[e] = c[e]; g_cur[e] = 0; run += c[e]; }
    }
}
__global__ void k_assign() {
    int t = blockIdx.x * blockDim.x + threadIdx.x;
    if (t >= NTOK) return;
    #pragma unroll
    for (int k = 0; k < KTOP; k++) {
        int e = g_idx[t*2+k];
        int p = atomicAdd(&g_cur[e], 1);
        int row = g_base[e] + p;
        g_loc[t*2+k] = row;
        g_rowtok[row] = t;
    }
}

// ================= GEMM1: h = silu(x W1^T) * (x W3^T), tf32 HMMA ==========
// CTA: 128 m-rows x 64 n-cols (per operand). 8 warps = 4m x 2n, warp 32x32.
__global__ __launch_bounds__(256) void k_ffn1(
    const float* __restrict__ x, const float* __restrict__ w1, const float* __restrict__ w3)
{
    __shared__ float As [128][36];
    __shared__ float B1s[64][36];
    __shared__ float B3s[64][36];

    int e = blockIdx.z, cnt = g_cnt[e], base = g_base[e];
    int m0 = blockIdx.y * 128;
    if (m0 >= cnt) return;
    int n0 = blockIdx.x * 64;
    int tid = threadIdx.x;

    // ---- loader roles ----
    int ar = tid >> 1, ac = (tid & 1) * 16;              // A: row, 16-float half
    bool aval = (m0 + ar) < cnt;
    int tok = aval ? g_rowtok[base + m0 + ar] : 0;
    const float* ap = x + (size_t)tok * DIM + ac;
    int br = tid >> 2, bc = (tid & 3) * 8;               // B: row, 8-float quarter
    const float* b1p = w1 + ((size_t)e*HID + n0 + br) * DIM + bc;
    const float* b3p = w3 + ((size_t)e*HID + n0 + br) * DIM + bc;

    // ---- compute roles ----
    int lane = tid & 31, g = lane >> 2, tg = lane & 3;
    int w = tid >> 5;
    int wm = (w >> 1) * 32, wn = (w & 1) * 32;

    float acc1[2][4][4] = {}, acc3[2][4][4] = {};
    float4 va[4], vb1[2], vb3[2];

    // prefetch chunk 0
    #pragma unroll
    for (int j = 0; j < 4; j++) va[j] = aval ? *(const float4*)(ap + j*4) : make_float4(0,0,0,0);
    vb1[0] = *(const float4*)(b1p);  vb1[1] = *(const float4*)(b1p + 4);
    vb3[0] = *(const float4*)(b3p);  vb3[1] = *(const float4*)(b3p + 4);

    for (int i = 0; i < DIM/BK; i++) {
        __syncthreads();
        #pragma unroll
        for (int j = 0; j < 4; j++) *(uint4*)&As[ar][ac + j*4] = rna4(va[j]);
        *(uint4*)&B1s[br][bc]     = rna4(vb1[0]);
        *(uint4*)&B1s[br][bc + 4] = rna4(vb1[1]);
        *(uint4*)&B3s[br][bc]     = rna4(vb3[0]);
        *(uint4*)&B3s[br][bc + 4] = rna4(vb3[1]);
        if (i + 1 < DIM/BK) {
            int ko = (i + 1) * BK;
            #pragma unroll
            for (int j = 0; j < 4; j++) va[j] = aval ? *(const float4*)(ap + ko + j*4) : make_float4(0,0,0,0);
            vb1[0] = *(const float4*)(b1p + ko);  vb1[1] = *(const float4*)(b1p + ko + 4);
            vb3[0] = *(const float4*)(b3p + ko);  vb3[1] = *(const float4*)(b3p + ko + 4);
        }
        __syncthreads();
        #pragma unroll
        for (int ks = 0; ks < 4; ks++) {
            int k0 = ks * 8;
            uint32_t a[2][4];
            #pragma unroll
            for (int f = 0; f < 2; f++) {
                int r0 = wm + f*16 + g;
                a[f][0] = __float_as_uint(As[r0    ][k0 + tg]);
                a[f][1] = __float_as_uint(As[r0 + 8][k0 + tg]);
                a[f][2] = __float_as_uint(As[r0    ][k0 + tg + 4]);
                a[f][3] = __float_as_uint(As[r0 + 8][k0 + tg + 4]);
            }
            #pragma unroll
            for (int j = 0; j < 4; j++) {
                int n = wn + j*8 + g;
                uint32_t b1f[2] = { __float_as_uint(B1s[n][k0 + tg]), __float_as_uint(B1s[n][k0 + tg + 4]) };
                uint32_t b3f[2] = { __float_as_uint(B3s[n][k0 + tg]), __float_as_uint(B3s[n][k0 + tg + 4]) };
                #pragma unroll
                for (int f = 0; f < 2; f++) {
                    mma8(acc1[f][j], a[f], b1f);
                    mma8(acc3[f][j], a[f], b3f);
                }
            }
        }
    }

    // ---- epilogue: silu(d1)*d3 -> g_h (tf32-rounded) ----
    #pragma unroll
    for (int f = 0; f < 2; f++) {
        #pragma unroll
        for (int rr = 0; rr < 2; rr++) {
            int m = wm + f*16 + rr*8 + g;
            if (m0 + m >= cnt) continue;
            size_t rowb = (size_t)(base + m0 + m) * HID + n0 + wn;
            #pragma unroll
            for (int j = 0; j < 4; j++) {
                float v0 = acc1[f][j][rr*2+0], v1 = acc1[f][j][rr*2+1];
                float h0 = v0 / (1.f + __expf(-v0)) * acc3[f][j][rr*2+0];
                float h1 = v1 / (1.f + __expf(-v1)) * acc3[f][j][rr*2+1];
                *(uint2*)&g_h[rowb + j*8 + 2*tg] = make_uint2(rna1(h0), rna1(h1));
            }
        }
    }
}

// ================= GEMM2: y = h W2^T, tf32 HMMA ===========================
// CTA: 128 x 128. 8 warps = 4m x 2n, warp 32x64.
__global__ __launch_bounds__(256) void k_ffn2(const float* __restrict__ w2)
{
    __shared__ float As[128][36];
    __shared__ float Bs[128][36];

    int e = blockIdx.z, cnt = g_cnt[e], base = g_base[e];
    int m0 = blockIdx.y * 128;
    if (m0 >= cnt) return;
    int n0 = blockIdx.x * 128;
    int tid = threadIdx.x;

    int ar = tid >> 1, ac = (tid & 1) * 16;
    bool aval = (m0 + ar) < cnt;
    int arow = aval ? (base + m0 + ar) : base;
    const float* ap = g_h + (size_t)arow * HID + ac;
    const float* bp = w2 + ((size_t)e*DIM + n0 + ar) * HID + ac;  // B uses same row/half pattern

    int lane = tid & 31, g = lane >> 2, tg = lane & 3;
    int w = tid >> 5;
    int wm = (w >> 1) * 32, wn = (w & 1) * 64;

    float acc[2][8][4] = {};
    float4 va[4], vb[4];

    #pragma unroll
    for (int j = 0; j < 4; j++) {
        va[j] = aval ? *(const float4*)(ap + j*4) : make_float4(0,0,0,0);
        vb[j] = *(const float4*)(bp + j*4);
    }

    for (int i = 0; i < HID/BK; i++) {
        __syncthreads();
        #pragma unroll
        for (int j = 0; j < 4; j++) {
            *(float4*)&As[ar][ac + j*4] = va[j];          // g_h already tf32-rounded
            *(uint4*)&Bs[ar][ac + j*4]  = rna4(vb[j]);
        }
        if (i + 1 < HID/BK) {
            int ko = (i + 1) * BK;
            #pragma unroll
            for (int j = 0; j < 4; j++) {
                va[j] = aval ? *(const float4*)(ap + ko + j*4) : make_float4(0,0,0,0);
                vb[j] = *(const float4*)(bp + ko + j*4);
            }
        }
        __syncthreads();
        #pragma unroll
        for (int ks = 0; ks < 4; ks++) {
            int k0 = ks * 8;
            uint32_t a[2][4];
            #pragma unroll
            for (int f = 0; f < 2; f++) {
                int r0 = wm + f*16 + g;
                a[f][0] = __float_as_uint(As[r0    ][k0 + tg]);
                a[f][1] = __float_as_uint(As[r0 + 8][k0 + tg]);
                a[f][2] = __float_as_uint(As[r0    ][k0 + tg + 4]);
                a[f][3] = __float_as_uint(As[r0 + 8][k0 + tg + 4]);
            }
            #pragma unroll
            for (int j = 0; j < 8; j++) {
                int n = wn + j*8 + g;
                uint32_t bf[2] = { __float_as_uint(Bs[n][k0 + tg]), __float_as_uint(Bs[n][k0 + tg + 4]) };
                #pragma unroll
                for (int f = 0; f < 2; f++) mma8(acc[f][j], a[f], bf);
            }
        }
    }

    #pragma unroll
    for (int f = 0; f < 2; f++) {
        #pragma unroll
        for (int rr = 0; rr < 2; rr++) {
            int m = wm + f*16 + rr*8 + g;
            if (m0 + m >= cnt) continue;
            size_t rowb = (size_t)(base + m0 + m) * DIM + n0 + wn;
            #pragma unroll
            for (int j = 0; j < 8; j++) {
                *(float2*)&g_y[rowb + j*8 + 2*tg] =
                    make_float2(acc[f][j][rr*2+0], acc[f][j][rr*2+1]);
            }
        }
    }
}

// ---------------- combine ----------------
__global__ void k_combine(float* __restrict__ out) {
    int i = blockIdx.x * blockDim.x + threadIdx.x;
    if (i >= NTOK * (DIM/4)) return;
    int t = i / (DIM/4);
    int dq = i % (DIM/4);
    float w0 = g_wgt[t*2+0], w1 = g_wgt[t*2+1];
    int r0 = g_loc[t*2+0], r1 = g_loc[t*2+1];
    float4 y0 = *(const float4*)&g_y[(size_t)r0*DIM + dq*4];
    float4 y1 = *(const float4*)&g_y[(size_t)r1*DIM + dq*4];
    float4 o;
    o.x = w0*y0.x + w1*y1.x; o.y = w0*y0.y + w1*y1.y;
    o.z = w0*y0.z + w1*y1.z; o.w = w0*y0.w + w1*y1.w;
    *(float4*)(out + (size_t)i*4) = o;
}

// ---------------- launcher ----------------
extern "C" void kernel_launch(void* const* d_in, const int* in_sizes, int n_in,
                              void* d_out, int out_size) {
    const float* x  = (const float*)d_in[0];
    const float* gw = (const float*)d_in[1];
    const float* w1 = (const float*)d_in[2];
    const float* w2 = (const float*)d_in[3];
    const float* w3 = (const float*)d_in[4];
    float* out = (float*)d_out;

    k_gate<<<NTOK/8, 256>>>(x, gw);
    k_hist<<<1, 256>>>();
    k_assign<<<NTOK/256, 256>>>();

    dim3 g1(HID/64, NTOK/128, NEXP);    // (64, 16, 8)
    k_ffn1<<<g1, 256>>>(x, w1, w3);

    dim3 g2(DIM/128, NTOK/128, NEXP);   // (8, 16, 8)
    k_ffn2<<<g2, 256>>>(w2);

    k_combine<<<(NTOK*(DIM/4) + 255)/256, 256>>>(out);
}